// round 4
// baseline (speedup 1.0000x reference)
#include <cuda_runtime.h>
#include <cuda_fp16.h>
#include <cstdint>

// GCN_79568564126323: 2-layer GCN, N=200000, E=3200000, dims 4 -> 16 -> 1.
//
// Aggregate-before-matmul, normalization factored out of edge loops.
// R4: layer-1 edge RED accumulates in fp16x2 (half atomic-ALU width),
//     self-loop term added in f32; deg counter self-zeroing (no init kernel).

#define N_MAX 200000

__device__ int    g_cnt [N_MAX];   // zero-init; re-zeroed by k_prep each call
__device__ float  g_dinv[N_MAX];
__device__ float4 g_xs  [N_MAX];   // x * dinv  (f32, precise source for gathers)
__device__ uint2  g_agg [N_MAX];   // 2x half2 accumulator (starts/ends at 0)
__device__ float  g_zs  [N_MAX];   // z * dinv

// ---------------------------------------------------------------- kernels

__global__ void k_count_deg(const int* __restrict__ dst, int e) {
    int i  = blockIdx.x * blockDim.x + threadIdx.x;
    int e4 = e >> 2;
    if (i < e4) {
        int4 d = ((const int4*)dst)[i];
        atomicAdd(&g_cnt[d.x], 1);
        atomicAdd(&g_cnt[d.y], 1);
        atomicAdd(&g_cnt[d.z], 1);
        atomicAdd(&g_cnt[d.w], 1);
    } else {
        int t = (e4 << 2) + (i - e4);
        if (t < e) atomicAdd(&g_cnt[dst[t]], 1);
    }
}

// dinv = rsqrt(cnt+1); xs = x*dinv; zero agg; re-zero cnt for next replay
__global__ void k_prep(const float4* __restrict__ x, int n) {
    int i = blockIdx.x * blockDim.x + threadIdx.x;
    if (i >= n) return;
    float di = rsqrtf((float)(g_cnt[i] + 1));   // +1 = self loop
    g_cnt[i]  = 0;                              // ready for next replay
    g_dinv[i] = di;
    float4 xv = x[i];
    g_xs[i]  = make_float4(xv.x * di, xv.y * di, xv.z * di, xv.w * di);
    g_agg[i] = make_uint2(0u, 0u);              // fp16x2 zeros
}

__device__ __forceinline__ void red_h4(uint2* p, float4 v) {
    __half2 h01 = __floats2half2_rn(v.x, v.y);
    __half2 h23 = __floats2half2_rn(v.z, v.w);
    unsigned r0 = *(unsigned*)&h01;
    unsigned r1 = *(unsigned*)&h23;
    unsigned long long gp = (unsigned long long)__cvta_generic_to_global(p);
    asm volatile("red.global.add.noftz.v2.f16x2 [%0], {%1, %2};"
                 :: "l"(gp), "r"(r0), "r"(r1) : "memory");
}

// layer-1 edge scatter: agg[d] += (fp16) xs[s]   (4 edges per thread)
__global__ void k_scatter1(const int* __restrict__ src,
                           const int* __restrict__ dst, int e) {
    int i  = blockIdx.x * blockDim.x + threadIdx.x;
    int e4 = e >> 2;
    if (i < e4) {
        int4 s = ((const int4*)src)[i];
        int4 d = ((const int4*)dst)[i];
        float4 v0 = g_xs[s.x];
        float4 v1 = g_xs[s.y];
        float4 v2 = g_xs[s.z];
        float4 v3 = g_xs[s.w];
        red_h4(&g_agg[d.x], v0);
        red_h4(&g_agg[d.y], v1);
        red_h4(&g_agg[d.z], v2);
        red_h4(&g_agg[d.w], v3);
    } else {
        int t = (e4 << 2) + (i - e4);
        if (t < e) red_h4(&g_agg[dst[t]], g_xs[src[t]]);
    }
}

// per-node dense: a = (agg_f16 + xs_self)*dinv; h = a@W1+b1; z = relu(h)@W2;
// zs = z*dinv; out init = self-loop term zs
__global__ void k_dense(const float* __restrict__ W1,
                        const float* __restrict__ b1,
                        const float* __restrict__ W2,
                        float* __restrict__ out, int n) {
    int i = blockIdx.x * blockDim.x + threadIdx.x;
    if (i >= n) return;
    float  di = g_dinv[i];
    uint2  au = g_agg[i];
    float2 a01 = __half22float2(*(__half2*)&au.x);
    float2 a23 = __half22float2(*(__half2*)&au.y);
    float4 xs  = g_xs[i];                       // self-loop term (f32)
    float ax = (a01.x + xs.x) * di;
    float ay = (a01.y + xs.y) * di;
    float az = (a23.x + xs.z) * di;
    float aw = (a23.y + xs.w) * di;
    float z = 0.0f;
#pragma unroll
    for (int j = 0; j < 16; j++) {
        float h = b1[j];
        h = fmaf(ax, W1[ 0 + j], h);
        h = fmaf(ay, W1[16 + j], h);
        h = fmaf(az, W1[32 + j], h);
        h = fmaf(aw, W1[48 + j], h);
        h = fmaxf(h, 0.0f);
        z = fmaf(h, W2[j], z);
    }
    float zs = z * di;
    g_zs[i] = zs;
    out[i]  = zs;                               // self-loop contribution
}

// layer-2 edge scatter: out[d] += zs[s]   (f32, 4 edges per thread)
__global__ void k_scatter2(const int* __restrict__ src,
                           const int* __restrict__ dst,
                           float* __restrict__ out, int e) {
    int i  = blockIdx.x * blockDim.x + threadIdx.x;
    int e4 = e >> 2;
    if (i < e4) {
        int4 s = ((const int4*)src)[i];
        int4 d = ((const int4*)dst)[i];
        float v0 = g_zs[s.x];
        float v1 = g_zs[s.y];
        float v2 = g_zs[s.z];
        float v3 = g_zs[s.w];
        atomicAdd(&out[d.x], v0);
        atomicAdd(&out[d.y], v1);
        atomicAdd(&out[d.z], v2);
        atomicAdd(&out[d.w], v3);
    } else {
        int t = (e4 << 2) + (i - e4);
        if (t < e) atomicAdd(&out[dst[t]], g_zs[src[t]]);
    }
}

// final per-node scale: out = out*dinv + b2
__global__ void k_final(const float* __restrict__ b2,
                        float* __restrict__ out, int n) {
    int i = blockIdx.x * blockDim.x + threadIdx.x;
    if (i < n) out[i] = fmaf(out[i], g_dinv[i], b2[0]);
}

// ---------------------------------------------------------------- launch

extern "C" void kernel_launch(void* const* d_in, const int* in_sizes, int n_in,
                              void* d_out, int out_size) {
    const float* x   = (const float*)d_in[0];   // [N,4] f32
    const int*   ei  = (const int*)d_in[1];     // [2,E] int32
    const float* W1  = (const float*)d_in[2];   // [4,16]
    const float* b1  = (const float*)d_in[3];   // [16]
    const float* W2  = (const float*)d_in[4];   // [16,1]
    const float* b2  = (const float*)d_in[5];   // [1]
    float*       out = (float*)d_out;           // [N,1]

    const int n = in_sizes[0] / 4;
    const int e = in_sizes[1] / 2;
    const int* src = ei;
    const int* dst = ei + e;

    const int T  = 256;
    const int gn = (n + T - 1) / T;
    const int e4 = e >> 2;
    const int et = e4 + (e & 3);
    const int ge = (et + T - 1) / T;

    k_count_deg<<<ge, T>>>(dst, e);
    k_prep     <<<gn, T>>>((const float4*)x, n);
    k_scatter1 <<<ge, T>>>(src, dst, e);
    k_dense    <<<gn, T>>>(W1, b1, W2, out, n);
    k_scatter2 <<<ge, T>>>(src, dst, out, e);
    k_final    <<<gn, T>>>(b2, out, n);
}